// round 12
// baseline (speedup 1.0000x reference)
#include <cuda_runtime.h>
#include <cuda_bf16.h>
#include <cstdint>

#define DD 128
#define NPAPER 100000
#define NAUTHOR 50000
#define NTOT 250000
#define ETOT_MAX 600000

// ---------------- scratch (device globals) -----------------------------------
__device__ float g_hp[(size_t)NPAPER * DD];
__device__ float g_ha[(size_t)NAUTHOR * DD];
__device__ float g_wsp1[384 * DD];
__device__ float g_wsa1[256 * DD];
__device__ float g_wsp2[384 * DD];
__device__ float g_wsa2[256 * DD];

// unified CSR over all 3 edge types (built once, reused by both layers)
// node ids: cites-dst d -> d; writes-dst d -> 100000+d; wb-dst d -> 200000+d
__device__ int g_rp[NTOT + 1];
__device__ int g_ci[ETOT_MAX];
__device__ int g_pos[NTOT];
__device__ int g_bsums[256];

__device__ __forceinline__ uint32_t smem_u32(const void* p) {
    uint32_t a;
    asm("{ .reg .u64 t; cvta.to.shared.u64 t, %1; cvt.u32.u64 %0, t; }" : "=r"(a) : "l"(p));
    return a;
}
__device__ __forceinline__ uint32_t rna(uint32_t raw) {
    uint32_t u;
    asm("cvt.rna.tf32.f32 %0, %1;" : "=r"(u) : "f"(__uint_as_float(raw)));
    return u;
}
template <int N>
__device__ __forceinline__ void cpasync_wait() {
    asm volatile("cp.async.wait_group %0;" :: "n"(N) : "memory");
}
__device__ __forceinline__ void cpasync_commit() {
    asm volatile("cp.async.commit_group;" ::: "memory");
}
__device__ __forceinline__ void cpasync16(uint32_t dst, const void* src) {
    asm volatile("cp.async.ca.shared.global [%0], [%1], 16;"
                 :: "r"(dst), "l"(src) : "memory");
}

// ---------------- small utility kernels --------------------------------------
__global__ void zero_int_kernel(int* __restrict__ p, int n) {
    int i = blockIdx.x * blockDim.x + threadIdx.x;
    if (i < n) p[i] = 0;
}

__global__ void stack_kernel(const float* __restrict__ Wm, const float* __restrict__ Wr,
                             float* __restrict__ SP, float* __restrict__ SA) {
    int i = blockIdx.x * blockDim.x + threadIdx.x;
    if (i < 32768) {
        SP[i] = Wm[i];
    } else if (i < 49152) {
        int j = i - 32768;
        SP[i] = Wr[j] + Wr[16384 + j];
    } else if (i < 65536) {
        int j = i - 49152;
        SA[j] = Wm[32768 + j];
    } else if (i < 81920) {
        int j = i - 65536;
        SA[16384 + j] = Wr[32768 + j];
    }
}

// ---------------- unified CSR build ------------------------------------------
__global__ void hist3_kernel(const int* __restrict__ cd, const int* __restrict__ wd,
                             const int* __restrict__ bd, int* __restrict__ cnt,
                             int Ec, int Ew, int Eb) {
    int i = blockIdx.x * blockDim.x + threadIdx.x;
    int Etot = Ec + Ew + Eb;
    if (i >= Etot) return;
    int node;
    if (i < Ec)            node = cd[i];
    else if (i < Ec + Ew)  node = NPAPER + wd[i - Ec];
    else                   node = 2 * NPAPER + bd[i - Ec - Ew];
    atomicAdd(&cnt[node], 1);
}

__global__ void scan1_kernel(const int* __restrict__ cnt, int* __restrict__ rp,
                             int* __restrict__ bsums, int n) {
    __shared__ int sh[256];
    int t = threadIdx.x;
    int base = blockIdx.x * 1024 + t * 4;
    int v[4];
#pragma unroll
    for (int j = 0; j < 4; ++j) v[j] = (base + j < n) ? cnt[base + j] : 0;
    int tsum = v[0] + v[1] + v[2] + v[3];
    sh[t] = tsum;
    __syncthreads();
    for (int off = 1; off < 256; off <<= 1) {
        int x = sh[t];
        if (t >= off) x += sh[t - off];
        __syncthreads();
        sh[t] = x;
        __syncthreads();
    }
    int run = sh[t] - tsum;
#pragma unroll
    for (int j = 0; j < 4; ++j) {
        if (base + j < n) rp[base + j] = run;
        run += v[j];
    }
    if (t == 255) bsums[blockIdx.x] = sh[255];
}

__global__ void scan2_kernel(int* __restrict__ bsums, int nb) {
    __shared__ int sh[256];
    int t = threadIdx.x;
    int v = (t < nb) ? bsums[t] : 0;
    sh[t] = v;
    __syncthreads();
    for (int off = 1; off < 256; off <<= 1) {
        int x = sh[t];
        if (t >= off) x += sh[t - off];
        __syncthreads();
        sh[t] = x;
        __syncthreads();
    }
    if (t < nb) bsums[t] = sh[t] - v;
}

__global__ void scan3_kernel(int* __restrict__ rp, const int* __restrict__ bsums,
                             int n, int E) {
    int i = blockIdx.x * blockDim.x + threadIdx.x;
    if (i < n) rp[i] += bsums[i >> 10];
    if (i == 0) rp[n] = E;
}

__global__ void fill3_kernel(const int* __restrict__ cs, const int* __restrict__ cd,
                             const int* __restrict__ ws, const int* __restrict__ wd,
                             const int* __restrict__ bs, const int* __restrict__ bd,
                             const int* __restrict__ rp, int* __restrict__ pos,
                             int* __restrict__ ci, int Ec, int Ew, int Eb) {
    int i = blockIdx.x * blockDim.x + threadIdx.x;
    int Etot = Ec + Ew + Eb;
    if (i >= Etot) return;
    int node, s;
    if (i < Ec)           { node = cd[i];                        s = cs[i]; }
    else if (i < Ec + Ew) { node = NPAPER + wd[i - Ec];          s = ws[i - Ec]; }
    else                  { node = 2 * NPAPER + bd[i - Ec - Ew]; s = bs[i - Ec - Ew]; }
    int o = atomicAdd(&pos[node], 1);
    ci[rp[node] + o] = s;
}

// ---------------- fused gather+GEMM (tf32 mma.sync, pipelined W) -------------
// Per 128-row tile: for each K-segment, gather the 128x128 A panel straight
// into SMEM from CSR (mean) or from the root features (copy), then run the
// segment's 4 k-tiles. W tiles are cp.async double-buffered. No mean arrays.
#define AP 132                              // A panel stride (words); 132%32==4
#define WS 136                              // W smem stride (words)
#define APAN_W (128 * AP)                   // A panel words = 16896
#define WSTG_W (32 * WS)                    // W stage words = 4352
#define GEMM_SMEM ((APAN_W + 2 * WSTG_W) * 4)   // 102400 B
#define GP_BLOCKS 782
#define GA_BLOCKS 391

__global__ __launch_bounds__(256, 2)
void sage_gemm_fused(
    float* __restrict__ outP, const float* __restrict__ WP,
    const float* __restrict__ bP0, const float* __restrict__ bP1,
    float* __restrict__ outA, const float* __restrict__ WA,
    const float* __restrict__ bA0,
    const float* __restrict__ xP, const float* __restrict__ xA,
    const int* __restrict__ rp, const int* __restrict__ ci,
    int do_relu)
{
    extern __shared__ uint32_t smem[];
    float* Apan = (float*)smem;                       // [128][AP]
    const uint32_t sbase = smem_u32(smem);
    const uint32_t wsmem0 = sbase + APAN_W * 4u;      // W double buffer base

    const int tid = threadIdx.x;
    const int wid = tid >> 5;
    const int lane = tid & 31;
    const int group = lane >> 2;
    const int tig = lane & 3;
    const int wr = (wid & 3) * 32;
    const int wc = (wid >> 2) * 64;

    const int is_author = (blockIdx.x >= GP_BLOCKS);
    const int brow = is_author ? (blockIdx.x - GP_BLOCKS) : blockIdx.x;
    const int row0 = brow * 128;
    const int M = is_author ? NAUTHOR : NPAPER;
    const int nseg = is_author ? 2 : 3;
    const int nkt = nseg * 4;
    const float* Wstack = is_author ? WA : WP;
    const float* bias0 = is_author ? bA0 : bP0;
    const float* bias1 = is_author ? nullptr : bP1;
    float* out = is_author ? outA : outP;

    // segment descriptors: gather source, node base (or root copy)
    const float* seg_src[3];
    int seg_base[3];   // -1 => root copy
    if (is_author) {
        seg_src[0] = xP; seg_base[0] = 2 * NPAPER;   // wb neighbors are papers
        seg_src[1] = xA; seg_base[1] = -1;           // root
        seg_src[2] = nullptr; seg_base[2] = -1;
    } else {
        seg_src[0] = xP; seg_base[0] = 0;            // cites: paper neighbors
        seg_src[1] = xA; seg_base[1] = NPAPER;       // writes: author neighbors
        seg_src[2] = xP; seg_base[2] = -1;           // root
    }

    float acc[2][8][4];
#pragma unroll
    for (int am = 0; am < 2; ++am)
#pragma unroll
        for (int nb = 0; nb < 8; ++nb)
#pragma unroll
            for (int j = 0; j < 4; ++j) acc[am][nb][j] = 0.f;

    auto issueW = [&](int kt) {
        uint32_t wbase = wsmem0 + (uint32_t)((kt & 1) * WSTG_W) * 4u;
        const float* Wk = Wstack + (size_t)(kt * 32) * DD;
#pragma unroll
        for (int i = 0; i < 4; ++i) {
            int idx = tid + i * 256;
            int k = idx >> 5;
            int n4 = idx & 31;
            cpasync16(wbase + (uint32_t)(k * WS + n4 * 4) * 4u,
                      Wk + (size_t)k * DD + n4 * 4);
        }
        cpasync_commit();
    };

    issueW(0);

    for (int seg = 0; seg < nseg; ++seg) {
        // ---- gather/copy the 128x128 A panel for this segment ----
        const float* x = seg_src[seg];
        const int nbase = seg_base[seg];
#pragma unroll 1
        for (int rr = 0; rr < 16; ++rr) {
            int r = wid * 16 + rr;
            int gr = row0 + r;
            float4 a4 = make_float4(0.f, 0.f, 0.f, 0.f);
            if (gr < M) {
                if (nbase < 0) {
                    a4 = *(const float4*)(x + (size_t)gr * DD + lane * 4);
                } else {
                    int node = nbase + gr;
                    int s0 = __ldg(&rp[node]), s1 = __ldg(&rp[node + 1]);
                    int e = s0;
                    for (; e + 1 < s1; e += 2) {
                        int sA = __ldg(&ci[e]);
                        int sB = __ldg(&ci[e + 1]);
                        float4 a = *(const float4*)(x + (size_t)sA * DD + lane * 4);
                        float4 b = *(const float4*)(x + (size_t)sB * DD + lane * 4);
                        a4.x += a.x + b.x; a4.y += a.y + b.y;
                        a4.z += a.z + b.z; a4.w += a.w + b.w;
                    }
                    if (e < s1) {
                        int sA = __ldg(&ci[e]);
                        float4 a = *(const float4*)(x + (size_t)sA * DD + lane * 4);
                        a4.x += a.x; a4.y += a.y; a4.z += a.z; a4.w += a.w;
                    }
                    float inv = 1.0f / (float)max(s1 - s0, 1);
                    a4.x *= inv; a4.y *= inv; a4.z *= inv; a4.w *= inv;
                }
            }
            *(float4*)&Apan[r * AP + lane * 4] = a4;
        }
        __syncthreads();

        // ---- 4 k-tiles of this segment ----
#pragma unroll 1
        for (int kk = 0; kk < 4; ++kk) {
            int kt = seg * 4 + kk;
            if (kt + 1 < nkt) {
                issueW(kt + 1);
                cpasync_wait<1>();
            } else {
                cpasync_wait<0>();
            }
            __syncthreads();

            const uint32_t* As = smem + (uint32_t)(kk * 32);  // column offset in panel
            const uint32_t* Ws = smem + APAN_W + (kt & 1) * WSTG_W;

#pragma unroll
            for (int k0 = 0; k0 < 32; k0 += 8) {
                uint32_t a[2][4];
#pragma unroll
                for (int am = 0; am < 2; ++am) {
                    int rb = wr + am * 16;
                    a[am][0] = rna(As[(rb + group) * AP + k0 + tig]);
                    a[am][1] = rna(As[(rb + group + 8) * AP + k0 + tig]);
                    a[am][2] = rna(As[(rb + group) * AP + k0 + tig + 4]);
                    a[am][3] = rna(As[(rb + group + 8) * AP + k0 + tig + 4]);
                }
#pragma unroll
                for (int nb = 0; nb < 8; ++nb) {
                    uint32_t b0 = rna(Ws[(k0 + tig) * WS + wc + nb * 8 + group]);
                    uint32_t b1 = rna(Ws[(k0 + tig + 4) * WS + wc + nb * 8 + group]);
#pragma unroll
                    for (int am = 0; am < 2; ++am) {
                        asm volatile(
                            "mma.sync.aligned.m16n8k8.row.col.f32.tf32.tf32.f32 "
                            "{%0,%1,%2,%3}, {%4,%5,%6,%7}, {%8,%9}, {%0,%1,%2,%3};"
                            : "+f"(acc[am][nb][0]), "+f"(acc[am][nb][1]),
                              "+f"(acc[am][nb][2]), "+f"(acc[am][nb][3])
                            : "r"(a[am][0]), "r"(a[am][1]), "r"(a[am][2]), "r"(a[am][3]),
                              "r"(b0), "r"(b1));
                    }
                }
            }
            __syncthreads();
        }
    }

    // ---- epilogue ----
#pragma unroll
    for (int nb = 0; nb < 8; ++nb) {
        int col = wc + nb * 8 + 2 * tig;
        float bA = 0.f, bB = 0.f;
        if (bias0 != nullptr) { bA = bias0[col]; bB = bias0[col + 1]; }
        if (bias1 != nullptr) { bA += bias1[col]; bB += bias1[col + 1]; }
#pragma unroll
        for (int am = 0; am < 2; ++am) {
            int r_lo = row0 + wr + am * 16 + group;
            int r_hi = r_lo + 8;
            float v0 = acc[am][nb][0] + bA, v1 = acc[am][nb][1] + bB;
            float v2 = acc[am][nb][2] + bA, v3 = acc[am][nb][3] + bB;
            if (do_relu) {
                v0 = fmaxf(v0, 0.f); v1 = fmaxf(v1, 0.f);
                v2 = fmaxf(v2, 0.f); v3 = fmaxf(v3, 0.f);
            }
            if (r_lo < M) *(float2*)&out[(size_t)r_lo * DD + col] = make_float2(v0, v1);
            if (r_hi < M) *(float2*)&out[(size_t)r_hi * DD + col] = make_float2(v2, v3);
        }
    }
}

// ---------------- launch ----------------------------------------------------
static inline int ceil_div(long long a, int b) { return (int)((a + b - 1) / b); }

extern "C" void kernel_launch(void* const* d_in, const int* in_sizes, int n_in,
                              void* d_out, int out_size)
{
    const float* xp  = (const float*)d_in[0];
    const float* xa  = (const float*)d_in[1];
    const float* Wm1 = (const float*)d_in[2];
    const float* b1  = (const float*)d_in[3];
    const float* Wr1 = (const float*)d_in[4];
    const float* Wm2 = (const float*)d_in[5];
    const float* b2  = (const float*)d_in[6];
    const float* Wr2 = (const float*)d_in[7];
    const int* cs = (const int*)d_in[8];
    const int* cd = (const int*)d_in[9];
    const int* ws = (const int*)d_in[10];
    const int* wd = (const int*)d_in[11];
    const int* bs = (const int*)d_in[12];
    const int* bd = (const int*)d_in[13];
    const int Ec = in_sizes[8];
    const int Ew = in_sizes[10];
    const int Eb = in_sizes[12];
    const int Etot = Ec + Ew + Eb;

    float *hp, *ha, *wsp1, *wsa1, *wsp2, *wsa2;
    int *rp, *ci, *pos, *bsums;
    cudaGetSymbolAddress((void**)&hp,    g_hp);
    cudaGetSymbolAddress((void**)&ha,    g_ha);
    cudaGetSymbolAddress((void**)&wsp1,  g_wsp1);
    cudaGetSymbolAddress((void**)&wsa1,  g_wsa1);
    cudaGetSymbolAddress((void**)&wsp2,  g_wsp2);
    cudaGetSymbolAddress((void**)&wsa2,  g_wsa2);
    cudaGetSymbolAddress((void**)&rp,    g_rp);
    cudaGetSymbolAddress((void**)&ci,    g_ci);
    cudaGetSymbolAddress((void**)&pos,   g_pos);
    cudaGetSymbolAddress((void**)&bsums, g_bsums);

    cudaFuncSetAttribute(sage_gemm_fused, cudaFuncAttributeMaxDynamicSharedMemorySize, GEMM_SMEM);

    float* out_p = (float*)d_out;
    float* out_a = out_p + (size_t)NPAPER * DD;

    // ---- unified CSR build ----
    zero_int_kernel<<<ceil_div(NTOT, 256), 256>>>(pos, NTOT);
    hist3_kernel<<<ceil_div(Etot, 256), 256>>>(cd, wd, bd, pos, Ec, Ew, Eb);
    int nb = ceil_div(NTOT, 1024);
    scan1_kernel<<<nb, 256>>>(pos, rp, bsums, NTOT);
    scan2_kernel<<<1, 256>>>(bsums, nb);
    scan3_kernel<<<ceil_div(NTOT, 256), 256>>>(rp, bsums, NTOT, Etot);
    zero_int_kernel<<<ceil_div(NTOT, 256), 256>>>(pos, NTOT);
    fill3_kernel<<<ceil_div(Etot, 256), 256>>>(cs, cd, ws, wd, bs, bd, rp, pos, ci,
                                               Ec, Ew, Eb);

    // ---- stacked weights ----
    stack_kernel<<<320, 256>>>(Wm1, Wr1, wsp1, wsa1);
    stack_kernel<<<320, 256>>>(Wm2, Wr2, wsp2, wsa2);

    // ---- layer 1 (fused gather+GEMM) ----
    sage_gemm_fused<<<GP_BLOCKS + GA_BLOCKS, 256, GEMM_SMEM>>>(
        hp, wsp1, b1, b1 + DD,
        ha, wsa1, b1 + 2 * DD,
        xp, xa, rp, ci, 1);

    // ---- layer 2 ----
    sage_gemm_fused<<<GP_BLOCKS + GA_BLOCKS, 256, GEMM_SMEM>>>(
        out_p, wsp2, b2, b2 + DD,
        out_a, wsa2, b2 + 2 * DD,
        hp, ha, rp, ci, 0);
}

// round 13
// speedup vs baseline: 1.0721x; 1.0721x over previous
#include <cuda_runtime.h>
#include <cuda_bf16.h>
#include <cstdint>

#define DD 128
#define NPAPER 100000
#define NAUTHOR 50000
#define NTOT 250000
#define ETOT_MAX 600000

// ---------------- scratch (device globals) -----------------------------------
__device__ float g_mean_c[(size_t)NPAPER * DD];
__device__ float g_mean_w[(size_t)NPAPER * DD];
__device__ float g_mean_wb[(size_t)NAUTHOR * DD];
__device__ float g_hp[(size_t)NPAPER * DD];
__device__ float g_ha[(size_t)NAUTHOR * DD];
__device__ float g_wsp1[384 * DD];   // stacked + tf32-pre-rounded weights
__device__ float g_wsa1[256 * DD];
__device__ float g_wsp2[384 * DD];
__device__ float g_wsa2[256 * DD];

// unified CSR (built once, reused by both layers)
__device__ int g_rp[NTOT + 1];
__device__ int g_ci[ETOT_MAX];
__device__ int g_pos[NTOT];
__device__ int g_bsums[256];

__device__ __forceinline__ uint32_t smem_u32(const void* p) {
    uint32_t a;
    asm("{ .reg .u64 t; cvta.to.shared.u64 t, %1; cvt.u32.u64 %0, t; }" : "=r"(a) : "l"(p));
    return a;
}
__device__ __forceinline__ uint32_t rna(uint32_t raw) {
    uint32_t u;
    asm("cvt.rna.tf32.f32 %0, %1;" : "=r"(u) : "f"(__uint_as_float(raw)));
    return u;
}
__device__ __forceinline__ float rnaf(float x) {
    uint32_t u;
    asm("cvt.rna.tf32.f32 %0, %1;" : "=r"(u) : "f"(x));
    return __uint_as_float(u);
}
template <int N>
__device__ __forceinline__ void cpasync_wait() {
    asm volatile("cp.async.wait_group %0;" :: "n"(N) : "memory");
}
__device__ __forceinline__ void cpasync_commit() {
    asm volatile("cp.async.commit_group;" ::: "memory");
}
__device__ __forceinline__ void cpasync16(uint32_t dst, const void* src, int src_bytes) {
    asm volatile("cp.async.ca.shared.global [%0], [%1], 16, %2;"
                 :: "r"(dst), "l"(src), "r"(src_bytes) : "memory");
}

// ---------------- small utility kernels --------------------------------------
__global__ void zero_int_kernel(int* __restrict__ p, int n) {
    int i = blockIdx.x * blockDim.x + threadIdx.x;
    if (i < n) p[i] = 0;
}

// Stack + tf32-pre-round BOTH layers' weights in one launch.
// layer offset: l=0 -> (Wm1,Wr1,SP1,SA1); l=1 -> (Wm2,Wr2,SP2,SA2)
__global__ void stack2_kernel(const float* __restrict__ Wm1, const float* __restrict__ Wr1,
                              float* __restrict__ SP1, float* __restrict__ SA1,
                              const float* __restrict__ Wm2, const float* __restrict__ Wr2,
                              float* __restrict__ SP2, float* __restrict__ SA2) {
    int gi = blockIdx.x * blockDim.x + threadIdx.x;   // 0 .. 163839
    int l = gi >= 81920;
    int i = l ? gi - 81920 : gi;
    const float* Wm = l ? Wm2 : Wm1;
    const float* Wr = l ? Wr2 : Wr1;
    float* SP = l ? SP2 : SP1;
    float* SA = l ? SA2 : SA1;
    if (i < 32768) {
        SP[i] = rnaf(Wm[i]);
    } else if (i < 49152) {
        int j = i - 32768;
        SP[i] = rnaf(Wr[j] + Wr[16384 + j]);
    } else if (i < 65536) {
        int j = i - 49152;
        SA[j] = rnaf(Wm[32768 + j]);
    } else if (i < 81920) {
        int j = i - 65536;
        SA[16384 + j] = rnaf(Wr[32768 + j]);
    }
}

// ---------------- unified CSR build ------------------------------------------
__global__ void hist3_kernel(const int* __restrict__ cd, const int* __restrict__ wd,
                             const int* __restrict__ bd, int* __restrict__ cnt,
                             int Ec, int Ew, int Eb) {
    int i = blockIdx.x * blockDim.x + threadIdx.x;
    int Etot = Ec + Ew + Eb;
    if (i >= Etot) return;
    int node;
    if (i < Ec)            node = cd[i];
    else if (i < Ec + Ew)  node = NPAPER + wd[i - Ec];
    else                   node = 2 * NPAPER + bd[i - Ec - Ew];
    atomicAdd(&cnt[node], 1);
}

__global__ void scan1_kernel(const int* __restrict__ cnt, int* __restrict__ rp,
                             int* __restrict__ bsums, int n) {
    __shared__ int sh[256];
    int t = threadIdx.x;
    int base = blockIdx.x * 1024 + t * 4;
    int v[4];
#pragma unroll
    for (int j = 0; j < 4; ++j) v[j] = (base + j < n) ? cnt[base + j] : 0;
    int tsum = v[0] + v[1] + v[2] + v[3];
    sh[t] = tsum;
    __syncthreads();
    for (int off = 1; off < 256; off <<= 1) {
        int x = sh[t];
        if (t >= off) x += sh[t - off];
        __syncthreads();
        sh[t] = x;
        __syncthreads();
    }
    int run = sh[t] - tsum;
#pragma unroll
    for (int j = 0; j < 4; ++j) {
        if (base + j < n) rp[base + j] = run;
        run += v[j];
    }
    if (t == 255) bsums[blockIdx.x] = sh[255];
}

__global__ void scan2_kernel(int* __restrict__ bsums, int nb) {
    __shared__ int sh[256];
    int t = threadIdx.x;
    int v = (t < nb) ? bsums[t] : 0;
    sh[t] = v;
    __syncthreads();
    for (int off = 1; off < 256; off <<= 1) {
        int x = sh[t];
        if (t >= off) x += sh[t - off];
        __syncthreads();
        sh[t] = x;
        __syncthreads();
    }
    if (t < nb) bsums[t] = sh[t] - v;
}

// scan3 + re-zero fill cursors in one pass
__global__ void scan3z_kernel(int* __restrict__ rp, const int* __restrict__ bsums,
                              int* __restrict__ pos, int n, int E) {
    int i = blockIdx.x * blockDim.x + threadIdx.x;
    if (i < n) {
        rp[i] += bsums[i >> 10];
        pos[i] = 0;
    }
    if (i == 0) rp[n] = E;
}

__global__ void fill3_kernel(const int* __restrict__ cs, const int* __restrict__ cd,
                             const int* __restrict__ ws, const int* __restrict__ wd,
                             const int* __restrict__ bs, const int* __restrict__ bd,
                             const int* __restrict__ rp, int* __restrict__ pos,
                             int* __restrict__ ci, int Ec, int Ew, int Eb) {
    int i = blockIdx.x * blockDim.x + threadIdx.x;
    int Etot = Ec + Ew + Eb;
    if (i >= Etot) return;
    int node, s;
    if (i < Ec)           { node = cd[i];                        s = cs[i]; }
    else if (i < Ec + Ew) { node = NPAPER + wd[i - Ec];          s = ws[i - Ec]; }
    else                  { node = 2 * NPAPER + bd[i - Ec - Ew]; s = bs[i - Ec - Ew]; }
    int o = atomicAdd(&pos[node], 1);
    ci[rp[node] + o] = s;
}

// ---------------- merged gather: all 3 mean tensors, one launch ---------------
__global__ void gather3_kernel(const float* __restrict__ xP,
                               const float* __restrict__ xA,
                               const int* __restrict__ rp,
                               const int* __restrict__ ci,
                               float* __restrict__ mc,
                               float* __restrict__ mw,
                               float* __restrict__ mwb) {
    int w = (int)((blockIdx.x * (size_t)blockDim.x + threadIdx.x) >> 5);
    int lane = threadIdx.x & 31;
    if (w >= NTOT) return;
    const float* x;
    float* out;
    if (w < NPAPER)            { x = xP; out = mc  + (size_t)w * DD; }
    else if (w < 2 * NPAPER)   { x = xA; out = mw  + (size_t)(w - NPAPER) * DD; }
    else                       { x = xP; out = mwb + (size_t)(w - 2 * NPAPER) * DD; }

    int s0 = rp[w], s1 = rp[w + 1];
    float4 acc = make_float4(0.f, 0.f, 0.f, 0.f);
    int e = s0;
    for (; e + 1 < s1; e += 2) {
        int sA = __ldg(&ci[e]);
        int sB = __ldg(&ci[e + 1]);
        float4 a = *(const float4*)(x + (size_t)sA * DD + lane * 4);
        float4 b = *(const float4*)(x + (size_t)sB * DD + lane * 4);
        acc.x += a.x + b.x; acc.y += a.y + b.y;
        acc.z += a.z + b.z; acc.w += a.w + b.w;
    }
    if (e < s1) {
        int sA = __ldg(&ci[e]);
        float4 a = *(const float4*)(x + (size_t)sA * DD + lane * 4);
        acc.x += a.x; acc.y += a.y; acc.z += a.z; acc.w += a.w;
    }
    float inv = 1.0f / (float)max(s1 - s0, 1);
    acc.x *= inv; acc.y *= inv; acc.z *= inv; acc.w *= inv;
    *(float4*)(out + lane * 4) = acc;
}

// ---------------- pipelined tf32 GEMM, 3-stage, pre-rounded W ----------------
#define AS 36
#define WS 136
#define STG (128 * AS + 32 * WS)          // 8960 words / stage
#define NSTAGE 3
#define GEMM_SMEM (NSTAGE * STG * 4)      // 107520 B
#define GP_BLOCKS 782
#define GA_BLOCKS 391

__global__ __launch_bounds__(256, 2)
void sage_gemm_dual(
    float* __restrict__ outP, const float* __restrict__ P0,
    const float* __restrict__ P1, const float* __restrict__ P2,
    const float* __restrict__ WP, const float* __restrict__ bP0,
    const float* __restrict__ bP1,
    float* __restrict__ outA, const float* __restrict__ Q0,
    const float* __restrict__ Q1, const float* __restrict__ WA,
    const float* __restrict__ bA0,
    int do_relu)
{
    extern __shared__ uint32_t smem[];
    const uint32_t sbase = smem_u32(smem);

    const int tid = threadIdx.x;
    const int wid = tid >> 5;
    const int lane = tid & 31;
    const int group = lane >> 2;
    const int tig = lane & 3;
    const int wr = (wid & 3) * 32;
    const int wc = (wid >> 2) * 64;

    const int is_author = (blockIdx.x >= GP_BLOCKS);
    const int brow = is_author ? (blockIdx.x - GP_BLOCKS) : blockIdx.x;
    const int row0 = brow * 128;
    const int M = is_author ? NAUTHOR : NPAPER;
    const int nkt = is_author ? 8 : 12;

    const float* Aarr[3];
    const float* Wstack;
    const float* bias0;
    const float* bias1;
    float* out;
    if (is_author) {
        Aarr[0] = Q0; Aarr[1] = Q1; Aarr[2] = nullptr;
        Wstack = WA; bias0 = bA0; bias1 = nullptr; out = outA;
    } else {
        Aarr[0] = P0; Aarr[1] = P1; Aarr[2] = P2;
        Wstack = WP; bias0 = bP0; bias1 = bP1; out = outP;
    }

    float acc[2][8][4];
#pragma unroll
    for (int am = 0; am < 2; ++am)
#pragma unroll
        for (int nb = 0; nb < 8; ++nb)
#pragma unroll
            for (int j = 0; j < 4; ++j) acc[am][nb][j] = 0.f;

    auto issue = [&](int kt) {
        int s = kt % NSTAGE;
        uint32_t abase = sbase + (uint32_t)(s * STG) * 4u;
        uint32_t wbase = abase + 128u * AS * 4u;
        const float* A = Aarr[kt >> 2];
        int kin = (kt & 3) * 32;
#pragma unroll
        for (int i = 0; i < 4; ++i) {
            int idx = tid + i * 256;
            int r = idx >> 3;
            int c4 = idx & 7;
            int gr = row0 + r;
            const float* src = A + (size_t)gr * DD + kin + c4 * 4;
            cpasync16(abase + (uint32_t)(r * AS + c4 * 4) * 4u, src, gr < M ? 16 : 0);
        }
        const float* Wk = Wstack + (size_t)(kt * 32) * DD;
#pragma unroll
        for (int i = 0; i < 4; ++i) {
            int idx = tid + i * 256;
            int k = idx >> 5;
            int n4 = idx & 31;
            cpasync16(wbase + (uint32_t)(k * WS + n4 * 4) * 4u,
                      Wk + (size_t)k * DD + n4 * 4, 16);
        }
        cpasync_commit();
    };

    issue(0);
    if (nkt > 1) issue(1);
    for (int kt = 0; kt < nkt; ++kt) {
        if (kt + 2 < nkt) {
            issue(kt + 2);
            cpasync_wait<2>();
        } else if (kt + 1 < nkt) {
            cpasync_wait<1>();
        } else {
            cpasync_wait<0>();
        }
        __syncthreads();

        const uint32_t* As = smem + (kt % NSTAGE) * STG;
        const uint32_t* Ws = As + 128 * AS;

#pragma unroll
        for (int k0 = 0; k0 < 32; k0 += 8) {
            uint32_t a[2][4];
#pragma unroll
            for (int am = 0; am < 2; ++am) {
                int rb = wr + am * 16;
                a[am][0] = rna(As[(rb + group) * AS + k0 + tig]);
                a[am][1] = rna(As[(rb + group + 8) * AS + k0 + tig]);
                a[am][2] = rna(As[(rb + group) * AS + k0 + tig + 4]);
                a[am][3] = rna(As[(rb + group + 8) * AS + k0 + tig + 4]);
            }
#pragma unroll
            for (int nb = 0; nb < 8; ++nb) {
                uint32_t b0 = Ws[(k0 + tig) * WS + wc + nb * 8 + group];      // pre-rounded
                uint32_t b1 = Ws[(k0 + tig + 4) * WS + wc + nb * 8 + group];  // pre-rounded
#pragma unroll
                for (int am = 0; am < 2; ++am) {
                    asm volatile(
                        "mma.sync.aligned.m16n8k8.row.col.f32.tf32.tf32.f32 "
                        "{%0,%1,%2,%3}, {%4,%5,%6,%7}, {%8,%9}, {%0,%1,%2,%3};"
                        : "+f"(acc[am][nb][0]), "+f"(acc[am][nb][1]),
                          "+f"(acc[am][nb][2]), "+f"(acc[am][nb][3])
                        : "r"(a[am][0]), "r"(a[am][1]), "r"(a[am][2]), "r"(a[am][3]),
                          "r"(b0), "r"(b1));
                }
            }
        }
        __syncthreads();
    }

#pragma unroll
    for (int nb = 0; nb < 8; ++nb) {
        int col = wc + nb * 8 + 2 * tig;
        float bA = 0.f, bB = 0.f;
        if (bias0 != nullptr) { bA = bias0[col]; bB = bias0[col + 1]; }
        if (bias1 != nullptr) { bA += bias1[col]; bB += bias1[col + 1]; }
#pragma unroll
        for (int am = 0; am < 2; ++am) {
            int r_lo = row0 + wr + am * 16 + group;
            int r_hi = r_lo + 8;
            float v0 = acc[am][nb][0] + bA, v1 = acc[am][nb][1] + bB;
            float v2 = acc[am][nb][2] + bA, v3 = acc[am][nb][3] + bB;
            if (do_relu) {
                v0 = fmaxf(v0, 0.f); v1 = fmaxf(v1, 0.f);
                v2 = fmaxf(v2, 0.f); v3 = fmaxf(v3, 0.f);
            }
            if (r_lo < M) *(float2*)&out[(size_t)r_lo * DD + col] = make_float2(v0, v1);
            if (r_hi < M) *(float2*)&out[(size_t)r_hi * DD + col] = make_float2(v2, v3);
        }
    }
}

// ---------------- launch ----------------------------------------------------
static inline int ceil_div(long long a, int b) { return (int)((a + b - 1) / b); }

extern "C" void kernel_launch(void* const* d_in, const int* in_sizes, int n_in,
                              void* d_out, int out_size)
{
    const float* xp  = (const float*)d_in[0];
    const float* xa  = (const float*)d_in[1];
    const float* Wm1 = (const float*)d_in[2];
    const float* b1  = (const float*)d_in[3];
    const float* Wr1 = (const float*)d_in[4];
    const float* Wm2 = (const float*)d_in[5];
    const float* b2  = (const float*)d_in[6];
    const float* Wr2 = (const float*)d_in[7];
    const int* cs = (const int*)d_in[8];
    const int* cd = (const int*)d_in[9];
    const int* ws = (const int*)d_in[10];
    const int* wd = (const int*)d_in[11];
    const int* bs = (const int*)d_in[12];
    const int* bd = (const int*)d_in[13];
    const int Ec = in_sizes[8];
    const int Ew = in_sizes[10];
    const int Eb = in_sizes[12];
    const int Etot = Ec + Ew + Eb;

    float *mean_c, *mean_w, *mean_wb, *hp, *ha, *wsp1, *wsa1, *wsp2, *wsa2;
    int *rp, *ci, *pos, *bsums;
    cudaGetSymbolAddress((void**)&mean_c,  g_mean_c);
    cudaGetSymbolAddress((void**)&mean_w,  g_mean_w);
    cudaGetSymbolAddress((void**)&mean_wb, g_mean_wb);
    cudaGetSymbolAddress((void**)&hp,    g_hp);
    cudaGetSymbolAddress((void**)&ha,    g_ha);
    cudaGetSymbolAddress((void**)&wsp1,  g_wsp1);
    cudaGetSymbolAddress((void**)&wsa1,  g_wsa1);
    cudaGetSymbolAddress((void**)&wsp2,  g_wsp2);
    cudaGetSymbolAddress((void**)&wsa2,  g_wsa2);
    cudaGetSymbolAddress((void**)&rp,    g_rp);
    cudaGetSymbolAddress((void**)&ci,    g_ci);
    cudaGetSymbolAddress((void**)&pos,   g_pos);
    cudaGetSymbolAddress((void**)&bsums, g_bsums);

    cudaFuncSetAttribute(sage_gemm_dual, cudaFuncAttributeMaxDynamicSharedMemorySize, GEMM_SMEM);

    float* out_p = (float*)d_out;
    float* out_a = out_p + (size_t)NPAPER * DD;

    // ---- unified CSR build (6 launches) ----
    zero_int_kernel<<<ceil_div(NTOT, 256), 256>>>(pos, NTOT);
    hist3_kernel<<<ceil_div(Etot, 256), 256>>>(cd, wd, bd, pos, Ec, Ew, Eb);
    int nb = ceil_div(NTOT, 1024);
    scan1_kernel<<<nb, 256>>>(pos, rp, bsums, NTOT);
    scan2_kernel<<<1, 256>>>(bsums, nb);
    scan3z_kernel<<<ceil_div(NTOT, 256), 256>>>(rp, bsums, pos, NTOT, Etot);
    fill3_kernel<<<ceil_div(Etot, 256), 256>>>(cs, cd, ws, wd, bs, bd, rp, pos, ci,
                                               Ec, Ew, Eb);

    // ---- stacked + pre-rounded weights (1 launch) ----
    stack2_kernel<<<640, 256>>>(Wm1, Wr1, wsp1, wsa1, Wm2, Wr2, wsp2, wsa2);

    const int GGRID = ceil_div((long long)NTOT * 32, 256);

    // ---- layer 1 ----
    gather3_kernel<<<GGRID, 256>>>(xp, xa, rp, ci, mean_c, mean_w, mean_wb);
    sage_gemm_dual<<<GP_BLOCKS + GA_BLOCKS, 256, GEMM_SMEM>>>(
        hp, mean_c, mean_w, xp, wsp1, b1, b1 + DD,
        ha, mean_wb, xa, wsa1, b1 + 2 * DD, 1);

    // ---- layer 2 ----
    gather3_kernel<<<GGRID, 256>>>(hp, ha, rp, ci, mean_c, mean_w, mean_wb);
    sage_gemm_dual<<<GP_BLOCKS + GA_BLOCKS, 256, GEMM_SMEM>>>(
        out_p, mean_c, mean_w, hp, wsp2, b2, b2 + DD,
        out_a, mean_wb, ha, wsa2, b2 + 2 * DD, 0);
}

// round 14
// speedup vs baseline: 1.3130x; 1.2247x over previous
#include <cuda_runtime.h>
#include <cuda_bf16.h>
#include <cstdint>

#define DD 128
#define NPAPER 100000
#define NAUTHOR 50000
#define NTOT 250000
#define ETOT_MAX 600000

// ---------------- scratch (device globals) -----------------------------------
__device__ float g_mean_c[(size_t)NPAPER * DD];
__device__ float g_mean_w[(size_t)NPAPER * DD];
__device__ float g_mean_wb[(size_t)NAUTHOR * DD];
__device__ float g_hp[(size_t)NPAPER * DD];
__device__ float g_ha[(size_t)NAUTHOR * DD];
__device__ float g_wsp1[384 * DD];   // stacked + tf32-pre-rounded weights
__device__ float g_wsa1[256 * DD];
__device__ float g_wsp2[384 * DD];
__device__ float g_wsa2[256 * DD];

// unified CSR (built once, reused by both layers)
__device__ int g_rp[NTOT + 1];
__device__ int g_ci[ETOT_MAX];
__device__ int g_pos[NTOT];
__device__ int g_bsums[256];

__device__ __forceinline__ uint32_t smem_u32(const void* p) {
    uint32_t a;
    asm("{ .reg .u64 t; cvta.to.shared.u64 t, %1; cvt.u32.u64 %0, t; }" : "=r"(a) : "l"(p));
    return a;
}
__device__ __forceinline__ uint32_t rna(uint32_t raw) {
    uint32_t u;
    asm("cvt.rna.tf32.f32 %0, %1;" : "=r"(u) : "f"(__uint_as_float(raw)));
    return u;
}
__device__ __forceinline__ float rnaf(float x) {
    uint32_t u;
    asm("cvt.rna.tf32.f32 %0, %1;" : "=r"(u) : "f"(x));
    return __uint_as_float(u);
}
template <int N>
__device__ __forceinline__ void cpasync_wait() {
    asm volatile("cp.async.wait_group %0;" :: "n"(N) : "memory");
}
__device__ __forceinline__ void cpasync_commit() {
    asm volatile("cp.async.commit_group;" ::: "memory");
}
__device__ __forceinline__ void cpasync16(uint32_t dst, const void* src, int src_bytes) {
    asm volatile("cp.async.ca.shared.global [%0], [%1], 16, %2;"
                 :: "r"(dst), "l"(src), "r"(src_bytes) : "memory");
}

// ---------------- small utility kernels --------------------------------------
__global__ void zero_int_kernel(int* __restrict__ p, int n) {
    int i = blockIdx.x * blockDim.x + threadIdx.x;
    if (i < n) p[i] = 0;
}

// Stack + tf32-pre-round BOTH layers' weights in one launch.
__global__ void stack2_kernel(const float* __restrict__ Wm1, const float* __restrict__ Wr1,
                              float* __restrict__ SP1, float* __restrict__ SA1,
                              const float* __restrict__ Wm2, const float* __restrict__ Wr2,
                              float* __restrict__ SP2, float* __restrict__ SA2) {
    int gi = blockIdx.x * blockDim.x + threadIdx.x;   // 0 .. 163839
    int l = gi >= 81920;
    int i = l ? gi - 81920 : gi;
    const float* Wm = l ? Wm2 : Wm1;
    const float* Wr = l ? Wr2 : Wr1;
    float* SP = l ? SP2 : SP1;
    float* SA = l ? SA2 : SA1;
    if (i < 32768) {
        SP[i] = rnaf(Wm[i]);
    } else if (i < 49152) {
        int j = i - 32768;
        SP[i] = rnaf(Wr[j] + Wr[16384 + j]);
    } else if (i < 65536) {
        int j = i - 49152;
        SA[j] = rnaf(Wm[32768 + j]);
    } else if (i < 81920) {
        int j = i - 65536;
        SA[16384 + j] = rnaf(Wr[32768 + j]);
    }
}

// ---------------- unified CSR build ------------------------------------------
__global__ void hist3_kernel(const int* __restrict__ cd, const int* __restrict__ wd,
                             const int* __restrict__ bd, int* __restrict__ cnt,
                             int Ec, int Ew, int Eb) {
    int i = blockIdx.x * blockDim.x + threadIdx.x;
    int Etot = Ec + Ew + Eb;
    if (i >= Etot) return;
    int node;
    if (i < Ec)            node = cd[i];
    else if (i < Ec + Ew)  node = NPAPER + wd[i - Ec];
    else                   node = 2 * NPAPER + bd[i - Ec - Ew];
    atomicAdd(&cnt[node], 1);
}

__global__ void scan1_kernel(const int* __restrict__ cnt, int* __restrict__ rp,
                             int* __restrict__ bsums, int n) {
    __shared__ int sh[256];
    int t = threadIdx.x;
    int base = blockIdx.x * 1024 + t * 4;
    int v[4];
#pragma unroll
    for (int j = 0; j < 4; ++j) v[j] = (base + j < n) ? cnt[base + j] : 0;
    int tsum = v[0] + v[1] + v[2] + v[3];
    sh[t] = tsum;
    __syncthreads();
    for (int off = 1; off < 256; off <<= 1) {
        int x = sh[t];
        if (t >= off) x += sh[t - off];
        __syncthreads();
        sh[t] = x;
        __syncthreads();
    }
    int run = sh[t] - tsum;
#pragma unroll
    for (int j = 0; j < 4; ++j) {
        if (base + j < n) rp[base + j] = run;
        run += v[j];
    }
    if (t == 255) bsums[blockIdx.x] = sh[255];
}

__global__ void scan2_kernel(int* __restrict__ bsums, int nb) {
    __shared__ int sh[256];
    int t = threadIdx.x;
    int v = (t < nb) ? bsums[t] : 0;
    sh[t] = v;
    __syncthreads();
    for (int off = 1; off < 256; off <<= 1) {
        int x = sh[t];
        if (t >= off) x += sh[t - off];
        __syncthreads();
        sh[t] = x;
        __syncthreads();
    }
    if (t < nb) bsums[t] = sh[t] - v;
}

// scan3 + re-zero fill cursors in one pass
__global__ void scan3z_kernel(int* __restrict__ rp, const int* __restrict__ bsums,
                              int* __restrict__ pos, int n, int E) {
    int i = blockIdx.x * blockDim.x + threadIdx.x;
    if (i < n) {
        rp[i] += bsums[i >> 10];
        pos[i] = 0;
    }
    if (i == 0) rp[n] = E;
}

__global__ void fill3_kernel(const int* __restrict__ cs, const int* __restrict__ cd,
                             const int* __restrict__ ws, const int* __restrict__ wd,
                             const int* __restrict__ bs, const int* __restrict__ bd,
                             const int* __restrict__ rp, int* __restrict__ pos,
                             int* __restrict__ ci, int Ec, int Ew, int Eb) {
    int i = blockIdx.x * blockDim.x + threadIdx.x;
    int Etot = Ec + Ew + Eb;
    if (i >= Etot) return;
    int node, s;
    if (i < Ec)           { node = cd[i];                        s = cs[i]; }
    else if (i < Ec + Ew) { node = NPAPER + wd[i - Ec];          s = ws[i - Ec]; }
    else                  { node = 2 * NPAPER + bd[i - Ec - Ew]; s = bs[i - Ec - Ew]; }
    int o = atomicAdd(&pos[node], 1);
    ci[rp[node] + o] = s;
}

// ---------------- merged gather: all 3 mean tensors, one launch ---------------
__global__ void gather3_kernel(const float* __restrict__ xP,
                               const float* __restrict__ xA,
                               const int* __restrict__ rp,
                               const int* __restrict__ ci,
                               float* __restrict__ mc,
                               float* __restrict__ mw,
                               float* __restrict__ mwb) {
    int w = (int)((blockIdx.x * (size_t)blockDim.x + threadIdx.x) >> 5);
    int lane = threadIdx.x & 31;
    if (w >= NTOT) return;
    const float* x;
    float* out;
    if (w < NPAPER)            { x = xP; out = mc  + (size_t)w * DD; }
    else if (w < 2 * NPAPER)   { x = xA; out = mw  + (size_t)(w - NPAPER) * DD; }
    else                       { x = xP; out = mwb + (size_t)(w - 2 * NPAPER) * DD; }

    int s0 = rp[w], s1 = rp[w + 1];
    float4 acc = make_float4(0.f, 0.f, 0.f, 0.f);
    int e = s0;
    for (; e + 1 < s1; e += 2) {
        int sA = __ldg(&ci[e]);
        int sB = __ldg(&ci[e + 1]);
        float4 a = *(const float4*)(x + (size_t)sA * DD + lane * 4);
        float4 b = *(const float4*)(x + (size_t)sB * DD + lane * 4);
        acc.x += a.x + b.x; acc.y += a.y + b.y;
        acc.z += a.z + b.z; acc.w += a.w + b.w;
    }
    if (e < s1) {
        int sA = __ldg(&ci[e]);
        float4 a = *(const float4*)(x + (size_t)sA * DD + lane * 4);
        acc.x += a.x; acc.y += a.y; acc.z += a.z; acc.w += a.w;
    }
    float inv = 1.0f / (float)max(s1 - s0, 1);
    acc.x *= inv; acc.y *= inv; acc.z *= inv; acc.w *= inv;
    *(float4*)(out + lane * 4) = acc;
}

// ---------------- pipelined tf32 GEMM (R11 2-stage) + pre-rounded W ----------
#define AS 36
#define WS 136
#define STG (128 * AS + 32 * WS)
#define GEMM_SMEM (2 * STG * 4)           // 71680 B (R11 footprint)
#define GP_BLOCKS 782
#define GA_BLOCKS 391

__global__ __launch_bounds__(256, 2)
void sage_gemm_dual(
    float* __restrict__ outP, const float* __restrict__ P0,
    const float* __restrict__ P1, const float* __restrict__ P2,
    const float* __restrict__ WP, const float* __restrict__ bP0,
    const float* __restrict__ bP1,
    float* __restrict__ outA, const float* __restrict__ Q0,
    const float* __restrict__ Q1, const float* __restrict__ WA,
    const float* __restrict__ bA0,
    int do_relu)
{
    extern __shared__ uint32_t smem[];
    const uint32_t sbase = smem_u32(smem);

    const int tid = threadIdx.x;
    const int wid = tid >> 5;
    const int lane = tid & 31;
    const int group = lane >> 2;
    const int tig = lane & 3;
    const int wr = (wid & 3) * 32;
    const int wc = (wid >> 2) * 64;

    const int is_author = (blockIdx.x >= GP_BLOCKS);
    const int brow = is_author ? (blockIdx.x - GP_BLOCKS) : blockIdx.x;
    const int row0 = brow * 128;
    const int M = is_author ? NAUTHOR : NPAPER;
    const int nkt = is_author ? 8 : 12;

    const float* Aarr[3];
    const float* Wstack;
    const float* bias0;
    const float* bias1;
    float* out;
    if (is_author) {
        Aarr[0] = Q0; Aarr[1] = Q1; Aarr[2] = nullptr;
        Wstack = WA; bias0 = bA0; bias1 = nullptr; out = outA;
    } else {
        Aarr[0] = P0; Aarr[1] = P1; Aarr[2] = P2;
        Wstack = WP; bias0 = bP0; bias1 = bP1; out = outP;
    }

    float acc[2][8][4];
#pragma unroll
    for (int am = 0; am < 2; ++am)
#pragma unroll
        for (int nb = 0; nb < 8; ++nb)
#pragma unroll
            for (int j = 0; j < 4; ++j) acc[am][nb][j] = 0.f;

    auto issue = [&](int kt) {
        int s = kt & 1;
        uint32_t abase = sbase + (uint32_t)(s * STG) * 4u;
        uint32_t wbase = abase + 128u * AS * 4u;
        const float* A = Aarr[kt >> 2];
        int kin = (kt & 3) * 32;
#pragma unroll
        for (int i = 0; i < 4; ++i) {
            int idx = tid + i * 256;
            int r = idx >> 3;
            int c4 = idx & 7;
            int gr = row0 + r;
            const float* src = A + (size_t)gr * DD + kin + c4 * 4;
            cpasync16(abase + (uint32_t)(r * AS + c4 * 4) * 4u, src, gr < M ? 16 : 0);
        }
        const float* Wk = Wstack + (size_t)(kt * 32) * DD;
#pragma unroll
        for (int i = 0; i < 4; ++i) {
            int idx = tid + i * 256;
            int k = idx >> 5;
            int n4 = idx & 31;
            cpasync16(wbase + (uint32_t)(k * WS + n4 * 4) * 4u,
                      Wk + (size_t)k * DD + n4 * 4, 16);
        }
        cpasync_commit();
    };

    issue(0);
    for (int kt = 0; kt < nkt; ++kt) {
        if (kt + 1 < nkt) {
            issue(kt + 1);
            cpasync_wait<1>();
        } else {
            cpasync_wait<0>();
        }
        __syncthreads();

        const uint32_t* As = smem + (kt & 1) * STG;
        const uint32_t* Ws = As + 128 * AS;

#pragma unroll
        for (int k0 = 0; k0 < 32; k0 += 8) {
            uint32_t a[2][4];
#pragma unroll
            for (int am = 0; am < 2; ++am) {
                int rb = wr + am * 16;
                a[am][0] = rna(As[(rb + group) * AS + k0 + tig]);
                a[am][1] = rna(As[(rb + group + 8) * AS + k0 + tig]);
                a[am][2] = rna(As[(rb + group) * AS + k0 + tig + 4]);
                a[am][3] = rna(As[(rb + group + 8) * AS + k0 + tig + 4]);
            }
#pragma unroll
            for (int nb = 0; nb < 8; ++nb) {
                uint32_t b0 = Ws[(k0 + tig) * WS + wc + nb * 8 + group];      // pre-rounded
                uint32_t b1 = Ws[(k0 + tig + 4) * WS + wc + nb * 8 + group];  // pre-rounded
#pragma unroll
                for (int am = 0; am < 2; ++am) {
                    asm volatile(
                        "mma.sync.aligned.m16n8k8.row.col.f32.tf32.tf32.f32 "
                        "{%0,%1,%2,%3}, {%4,%5,%6,%7}, {%8,%9}, {%0,%1,%2,%3};"
                        : "+f"(acc[am][nb][0]), "+f"(acc[am][nb][1]),
                          "+f"(acc[am][nb][2]), "+f"(acc[am][nb][3])
                        : "r"(a[am][0]), "r"(a[am][1]), "r"(a[am][2]), "r"(a[am][3]),
                          "r"(b0), "r"(b1));
                }
            }
        }
        __syncthreads();
    }

#pragma unroll
    for (int nb = 0; nb < 8; ++nb) {
        int col = wc + nb * 8 + 2 * tig;
        float bA = 0.f, bB = 0.f;
        if (bias0 != nullptr) { bA = bias0[col]; bB = bias0[col + 1]; }
        if (bias1 != nullptr) { bA += bias1[col]; bB += bias1[col + 1]; }
#pragma unroll
        for (int am = 0; am < 2; ++am) {
            int r_lo = row0 + wr + am * 16 + group;
            int r_hi = r_lo + 8;
            float v0 = acc[am][nb][0] + bA, v1 = acc[am][nb][1] + bB;
            float v2 = acc[am][nb][2] + bA, v3 = acc[am][nb][3] + bB;
            if (do_relu) {
                v0 = fmaxf(v0, 0.f); v1 = fmaxf(v1, 0.f);
                v2 = fmaxf(v2, 0.f); v3 = fmaxf(v3, 0.f);
            }
            if (r_lo < M) *(float2*)&out[(size_t)r_lo * DD + col] = make_float2(v0, v1);
            if (r_hi < M) *(float2*)&out[(size_t)r_hi * DD + col] = make_float2(v2, v3);
        }
    }
}

// ---------------- launch ----------------------------------------------------
static inline int ceil_div(long long a, int b) { return (int)((a + b - 1) / b); }

extern "C" void kernel_launch(void* const* d_in, const int* in_sizes, int n_in,
                              void* d_out, int out_size)
{
    const float* xp  = (const float*)d_in[0];
    const float* xa  = (const float*)d_in[1];
    const float* Wm1 = (const float*)d_in[2];
    const float* b1  = (const float*)d_in[3];
    const float* Wr1 = (const float*)d_in[4];
    const float* Wm2 = (const float*)d_in[5];
    const float* b2  = (const float*)d_in[6];
    const float* Wr2 = (const float*)d_in[7];
    const int* cs = (const int*)d_in[8];
    const int* cd = (const int*)d_in[9];
    const int* ws = (const int*)d_in[10];
    const int* wd = (const int*)d_in[11];
    const int* bs = (const int*)d_in[12];
    const int* bd = (const int*)d_in[13];
    const int Ec = in_sizes[8];
    const int Ew = in_sizes[10];
    const int Eb = in_sizes[12];
    const int Etot = Ec + Ew + Eb;

    float *mean_c, *mean_w, *mean_wb, *hp, *ha, *wsp1, *wsa1, *wsp2, *wsa2;
    int *rp, *ci, *pos, *bsums;
    cudaGetSymbolAddress((void**)&mean_c,  g_mean_c);
    cudaGetSymbolAddress((void**)&mean_w,  g_mean_w);
    cudaGetSymbolAddress((void**)&mean_wb, g_mean_wb);
    cudaGetSymbolAddress((void**)&hp,    g_hp);
    cudaGetSymbolAddress((void**)&ha,    g_ha);
    cudaGetSymbolAddress((void**)&wsp1,  g_wsp1);
    cudaGetSymbolAddress((void**)&wsa1,  g_wsa1);
    cudaGetSymbolAddress((void**)&wsp2,  g_wsp2);
    cudaGetSymbolAddress((void**)&wsa2,  g_wsa2);
    cudaGetSymbolAddress((void**)&rp,    g_rp);
    cudaGetSymbolAddress((void**)&ci,    g_ci);
    cudaGetSymbolAddress((void**)&pos,   g_pos);
    cudaGetSymbolAddress((void**)&bsums, g_bsums);

    cudaFuncSetAttribute(sage_gemm_dual, cudaFuncAttributeMaxDynamicSharedMemorySize, GEMM_SMEM);

    float* out_p = (float*)d_out;
    float* out_a = out_p + (size_t)NPAPER * DD;

    // ---- unified CSR build (6 launches) ----
    zero_int_kernel<<<ceil_div(NTOT, 256), 256>>>(pos, NTOT);
    hist3_kernel<<<ceil_div(Etot, 256), 256>>>(cd, wd, bd, pos, Ec, Ew, Eb);
    int nb = ceil_div(NTOT, 1024);
    scan1_kernel<<<nb, 256>>>(pos, rp, bsums, NTOT);
    scan2_kernel<<<1, 256>>>(bsums, nb);
    scan3z_kernel<<<ceil_div(NTOT, 256), 256>>>(rp, bsums, pos, NTOT, Etot);
    fill3_kernel<<<ceil_div(Etot, 256), 256>>>(cs, cd, ws, wd, bs, bd, rp, pos, ci,
                                               Ec, Ew, Eb);

    // ---- stacked + pre-rounded weights (1 launch) ----
    stack2_kernel<<<640, 256>>>(Wm1, Wr1, wsp1, wsa1, Wm2, Wr2, wsp2, wsa2);

    const int GGRID = ceil_div((long long)NTOT * 32, 256);

    // ---- layer 1 ----
    gather3_kernel<<<GGRID, 256>>>(xp, xa, rp, ci, mean_c, mean_w, mean_wb);
    sage_gemm_dual<<<GP_BLOCKS + GA_BLOCKS, 256, GEMM_SMEM>>>(
        hp, mean_c, mean_w, xp, wsp1, b1, b1 + DD,
        ha, mean_wb, xa, wsa1, b1 + 2 * DD, 1);

    // ---- layer 2 ----
    gather3_kernel<<<GGRID, 256>>>(hp, ha, rp, ci, mean_c, mean_w, mean_wb);
    sage_gemm_dual<<<GP_BLOCKS + GA_BLOCKS, 256, GEMM_SMEM>>>(
        out_p, mean_c, mean_w, hp, wsp2, b2, b2 + DD,
        out_a, mean_wb, ha, wsa2, b2 + 2 * DD, 0);
}